// round 12
// baseline (speedup 1.0000x reference)
#include <cuda_runtime.h>
#include <cstdint>

// Problem constants
#define NB      32
#define CDIM    256
#define HWN     4096
#define KCODES  1024
#define N_VEC   (NB * HWN)        // 131072
#define N_ZQ    (NB * CDIM * HWN) // 33554432

#define MARGIN  2.0e-3f
#define CINF    3.4e38f
#define NKQ     64                // k-quads (256/4)

// ---------------- static device scratch ----------------
__device__ uint32_t g_e8[NKQ * KCODES];  // packed int8 codebook [kq][n]
__device__ float    g_se[KCODES];        // ||e||^2 (exact fp32)
__device__ float    g_sc[KCODES];        // per-code dequant: codemax/127
__device__ double   g_loss;

__device__ __forceinline__ uint32_t smem_u32(const void* p) {
    uint32_t a;
    asm("{ .reg .u64 t; cvta.to.shared.u64 t, %1; cvt.u32.u64 %0, t; }"
        : "=r"(a) : "l"(p));
    return a;
}
#define CP_ASYNC16(dst, src) \
    asm volatile("cp.async.cg.shared.global [%0], [%1], 16;" :: "r"(dst), "l"(src))
#define CP_COMMIT() asm volatile("cp.async.commit_group;" ::: "memory")
#define CP_WAIT(n)  asm volatile("cp.async.wait_group %0;" :: "n"(n) : "memory")

// ---------------------------------------------------------------------------
// Codebook prep: exact ||e||^2, per-code maxabs, int8 pack into [kq][n].
// ---------------------------------------------------------------------------
__global__ void cb_prep_kernel(const float* __restrict__ cb) {
    int n = blockIdx.x, t = threadIdx.x;
    float v = cb[n * CDIM + t];
    __shared__ float red[256];
    __shared__ float sh_e[256];
    __shared__ float qs_sh;
    sh_e[t] = v;
    red[t] = __fmul_rn(v, v);
    __syncthreads();
    for (int s = 128; s > 0; s >>= 1) {
        if (t < s) red[t] = __fadd_rn(red[t], red[t + s]);
        __syncthreads();
    }
    if (t == 0) {
        g_se[n] = red[0];
        if (n == 0) g_loss = 0.0;
    }
    __syncthreads();
    red[t] = fabsf(v);
    __syncthreads();
    for (int s = 128; s > 0; s >>= 1) {
        if (t < s) red[t] = fmaxf(red[t], red[t + s]);
        __syncthreads();
    }
    if (t == 0) {
        float mx = red[0];
        g_sc[n] = mx * (1.0f / 127.0f);
        qs_sh = (mx > 0.0f) ? (127.0f / mx) : 0.0f;
    }
    __syncthreads();
    float qs = qs_sh;
    if (t < 64) {
        int q[4];
#pragma unroll
        for (int j = 0; j < 4; j++) {
            float x = sh_e[t * 4 + j] * qs;
            x = fminf(fmaxf(x, -127.0f), 127.0f);
            q[j] = __float2int_rn(x);
        }
        g_e8[t * KCODES + n] = (uint32_t)((q[0] & 255) | ((q[1] & 255) << 8) |
                                          ((q[2] & 255) << 16) | ((q[3] & 255) << 24));
    }
}

// ---------------------------------------------------------------------------
// Fused main: int8 dp4a prefilter GEMM + margin filter + exact in-CTA
// rescore + sz + gather/loss/indices. 256 threads, 128 vecs x 1024 codes.
// Thread (mg=tid>>4, ng=tid&15): m in {mg*4+j, 64+mg*4+j}, n quads likewise.
// ---------------------------------------------------------------------------
#define SM_ZS  0         // 131072 : z fp32 [256k][128m]
#define SM_Z8  131072    // 32768  : z int8 packed [64kq][128m] u32
#define SM_B   163840    // 2x8192 : B chunk [16kq][128n] u32
#define SM_SE  180224    // 4096
#define SM_SC  184320    // 4096
#define SM_SZ  188416    // 512
#define SM_DQ  188928    // 512 : rowmax/127
#define SM_QS  189440    // 512 : 127/rowmax
#define SM_IDX 189952    // 512
#define SM_CNT 190464    // 32
#define SM_TOT 190496
// resolution overlay inside [SM_Z8, SM_B+16384):
#define OV_RM    131072  // 128 x 17 f32 (padded)
#define OV_GMIN  147968  // 512
#define OV_PAIR  148480  // 2048 u32
#define OV_KEY   156672  // 128 u64
#define OV_CNTM  157696  // 128 int
#define OV_OVF   158208  // 128 int
#define OV_LASTN 158720  // 128 int
#define OV_OVFL  159232  // 128 int

__global__ void __launch_bounds__(256, 1)
vq_main_kernel(const float* __restrict__ z, const float* __restrict__ cb,
               float* __restrict__ out, int mode) {
    extern __shared__ __align__(1024) float smf[];
    char* sm = (char*)smf;
    const uint32_t sb = smem_u32(sm);
    const int tid = threadIdx.x;
    const int w = tid >> 5, lane = tid & 31;
    const int mg = tid >> 4, ng = tid & 15;
    const int m0 = blockIdx.x * 128;
    const int b   = m0 >> 12;
    const int hw0 = m0 & (HWN - 1);

    float* zS  = smf;
    float* seS = (float*)(sm + SM_SE);
    float* scS = (float*)(sm + SM_SC);
    float* szS = (float*)(sm + SM_SZ);
    float* dqS = (float*)(sm + SM_DQ);
    float* qsS = (float*)(sm + SM_QS);
    int*   idxS = (int*)(sm + SM_IDX);
    uint32_t* z8S = (uint32_t*)(sm + SM_Z8);

    for (int i = tid; i < KCODES; i += 256) { seS[i] = g_se[i]; scS[i] = g_sc[i]; }

    // z tile: [256 k][128 m] fp32, coalesced
    for (int it = 0; it < 32; it++) {
        int idx = tid + it * 256;
        int c = idx >> 5, mq = idx & 31;
        float4 v = *(const float4*)(z + (((size_t)(b * CDIM + c)) << 12) + hw0 + (mq << 2));
        *(float4*)(zS + c * 128 + (mq << 2)) = v;
    }
    // prefetch B chunk 0 (tile 0): [16kq][128n]
#pragma unroll
    for (int it = 0; it < 2; it++) {
        int idx = tid + it * 256;
        int row = idx >> 5, col = idx & 31;
        CP_ASYNC16(sb + SM_B + row * 512 + col * 16, g_e8 + row * KCODES + col * 4);
    }
    CP_COMMIT();
    __syncthreads();

    // sz (reference order: serial ascending c, unfused) + rowmax
    if (tid < 128) {
        float a = 0.0f, am = 0.0f;
        for (int c = 0; c < CDIM; c++) {
            float x = zS[c * 128 + tid];
            a = __fadd_rn(a, __fmul_rn(x, x));
            am = fmaxf(am, fabsf(x));
        }
        szS[tid] = a;
        dqS[tid] = am * (1.0f / 127.0f);
        qsS[tid] = (am > 0.0f) ? (127.0f / am) : 0.0f;
    }
    __syncthreads();

    // quantize z -> z8S [kq][m]
    for (int it = 0; it < 32; it++) {
        int idx = tid + it * 256;
        int kq = idx >> 7, m = idx & 127;
        float qs = qsS[m];
        int q[4];
#pragma unroll
        for (int j = 0; j < 4; j++) {
            float x = zS[(kq * 4 + j) * 128 + m] * qs;
            x = fminf(fmaxf(x, -127.0f), 127.0f);
            q[j] = __float2int_rn(x);
        }
        z8S[kq * 128 + m] = (uint32_t)((q[0] & 255) | ((q[1] & 255) << 8) |
                                       ((q[2] & 255) << 16) | ((q[3] & 255) << 24));
    }

    // per-thread margin-scan state: 8 m rows, 2 candidate slots each
    float rm[8], c0d[8], c1d[8];
    int c0i[8], c1i[8];
    unsigned ovfm = 0;
#pragma unroll
    for (int i = 0; i < 8; i++) { rm[i] = CINF; c0d[i] = CINF; c1d[i] = CINF; c0i[i] = 0; c1i[i] = 0; }

    int acc[64];
#pragma unroll
    for (int i = 0; i < 64; i++) acc[i] = 0;

    __syncthreads();

    // GEMM: 32 chunks = 8 tiles(128n) x 4 kq-chunks(16kq)
    for (int cidx = 0; cidx < 32; cidx++) {
        if (cidx + 1 < 32) {
            int t2 = (cidx + 1) >> 2, ch2 = (cidx + 1) & 3;
#pragma unroll
            for (int it = 0; it < 2; it++) {
                int idx = tid + it * 256;
                int row = idx >> 5, col = idx & 31;
                CP_ASYNC16(sb + SM_B + ((cidx + 1) & 1) * 8192 + row * 512 + col * 16,
                           g_e8 + (size_t)(ch2 * 16 + row) * KCODES + t2 * 128 + col * 4);
            }
            CP_COMMIT();
            CP_WAIT(1);
        } else {
            CP_WAIT(0);
        }
        __syncthreads();

        const uint32_t* bT = (const uint32_t*)(sm + SM_B + (cidx & 1) * 8192);
        const int ch = cidx & 3;
#pragma unroll
        for (int kqc = 0; kqc < 16; kqc++) {
            const uint32_t* Ap = z8S + (ch * 16 + kqc) * 128 + mg * 4;
            uint4 a0 = *(const uint4*)Ap;          // m = mg*4..+3
            uint4 a1 = *(const uint4*)(Ap + 64);   // m = 64+mg*4..+3
            const uint32_t* Bp = bT + kqc * 128 + ng * 4;
            uint4 b0 = *(const uint4*)Bp;          // n = ng*4..+3
            uint4 b1 = *(const uint4*)(Bp + 64);   // n = 64+ng*4..+3
            uint32_t av[8] = {a0.x, a0.y, a0.z, a0.w, a1.x, a1.y, a1.z, a1.w};
            uint32_t bv[8] = {b0.x, b0.y, b0.z, b0.w, b1.x, b1.y, b1.z, b1.w};
#pragma unroll
            for (int mi = 0; mi < 8; mi++)
#pragma unroll
                for (int ni = 0; ni < 8; ni++)
                    acc[mi * 8 + ni] = __dp4a((int)av[mi], (int)bv[ni], acc[mi * 8 + ni]);
        }
        __syncthreads();

        if ((cidx & 3) == 3) {
            // epilogue for tile cidx>>2: approx dist + margin-candidate update
            const int t2 = cidx >> 2;
#pragma unroll
            for (int ni = 0; ni < 8; ni++) {
                const int n = t2 * 128 + ((ni >> 2) << 6) + ng * 4 + (ni & 3);
                const float se = seS[n], sc = scS[n];
#pragma unroll
                for (int mi = 0; mi < 8; mi++) {
                    const int m = ((mi >> 2) << 6) + mg * 4 + (mi & 3);
                    float dot = (float)acc[mi * 8 + ni] * dqS[m] * sc;
                    float d = szS[m] + se - 2.0f * dot;
                    if (d < rm[mi] + MARGIN) {
                        if (d < rm[mi]) rm[mi] = d;
                        if (!(ovfm & (1u << mi))) {
                            if (c0d[mi] >= rm[mi] + MARGIN) {
                                c0d[mi] = c1d[mi]; c0i[mi] = c1i[mi]; c1d[mi] = CINF;
                            }
                            if (c1d[mi] >= rm[mi] + MARGIN) c1d[mi] = CINF;
                            if (c0d[mi] == CINF)      { c0d[mi] = d; c0i[mi] = n; }
                            else if (c1d[mi] == CINF) { c1d[mi] = d; c1i[mi] = n; }
                            else ovfm |= (1u << mi);
                        }
                    }
                }
            }
#pragma unroll
            for (int i = 0; i < 64; i++) acc[i] = 0;
        }
    }

    // ---- resolution ----
    float* RMS   = (float*)(sm + OV_RM);              // [128][17]
    float* gminS = (float*)(sm + OV_GMIN);
    uint32_t* pairs = (uint32_t*)(sm + OV_PAIR);
    unsigned long long* keyS = (unsigned long long*)(sm + OV_KEY);
    int* cntmS = (int*)(sm + OV_CNTM);
    int* ovfS  = (int*)(sm + OV_OVF);
    int* lastnS = (int*)(sm + OV_LASTN);
    int* ovflS  = (int*)(sm + OV_OVFL);
    int* cnt2   = (int*)(sm + SM_CNT);

    if (tid < 128) { cntmS[tid] = 0; ovfS[tid] = 0; keyS[tid] = ~0ull; lastnS[tid] = 0; }
    if (tid == 0) { cnt2[0] = 0; cnt2[1] = 0; }
    __syncthreads();

#pragma unroll
    for (int mi = 0; mi < 8; mi++) {
        const int m = ((mi >> 2) << 6) + mg * 4 + (mi & 3);
        RMS[m * 17 + ng] = rm[mi];
        if (ovfm & (1u << mi)) atomicOr(&ovfS[m], 1);
    }
    __syncthreads();

    if (tid < 128) {
        float gm = CINF;
#pragma unroll 8
        for (int p = 0; p < 16; p++) gm = fminf(gm, RMS[tid * 17 + p]);
        gminS[tid] = gm;
    }
    __syncthreads();

#pragma unroll
    for (int mi = 0; mi < 8; mi++) {
        const int m = ((mi >> 2) << 6) + mg * 4 + (mi & 3);
        if (ovfS[m]) continue;
        float gm = gminS[m];
        if (c0d[mi] != CINF && c0d[mi] < gm + MARGIN) {
            int p = atomicAdd(&cnt2[0], 1);
            if (p < 2048) { pairs[p] = (uint32_t)((m << 10) | c0i[mi]); atomicAdd(&cntmS[m], 1); lastnS[m] = c0i[mi]; }
            else atomicExch(&ovfS[m], 1);
        }
        if (c1d[mi] != CINF && c1d[mi] < gm + MARGIN) {
            int p = atomicAdd(&cnt2[0], 1);
            if (p < 2048) { pairs[p] = (uint32_t)((m << 10) | c1i[mi]); atomicAdd(&cntmS[m], 1); lastnS[m] = c1i[mi]; }
            else atomicExch(&ovfS[m], 1);
        }
    }
    __syncthreads();

    if (tid < 128) {
        if (ovfS[tid] || cntmS[tid] == 0) {
            int o = atomicAdd(&cnt2[1], 1);
            ovflS[o] = tid;
        } else if (cntmS[tid] == 1) {
            idxS[tid] = lastnS[tid];
        }
    }
    __syncthreads();

    // exact pair rescore (bitwise reference recipe)
    const int np = min(cnt2[0], 2048);
    for (int p = tid; p < np; p += 256) {
        uint32_t e = pairs[p];
        int m = e >> 10, n = e & 1023;
        if (ovfS[m] || cntmS[m] == 1) continue;
        const float* er = cb + (size_t)n * CDIM;
        float a2 = 0.0f;
#pragma unroll 16
        for (int k = 0; k < CDIM; k++) a2 = __fmaf_rn(zS[k * 128 + m], __ldg(er + k), a2);
        float d = __fsub_rn(__fadd_rn(szS[m], seS[n]), __fmul_rn(2.0f, a2));
        unsigned long long kk = ((unsigned long long)__float_as_uint(d) << 32) | (unsigned)n;
        atomicMin(&keyS[m], kk);
    }

    // exact full rescan for overflow rows (warp per row)
    const int novf = cnt2[1];
    for (int o = w; o < novf; o += 8) {
        int row = ovflS[o];
        float sz = szS[row];
        float bd = __int_as_float(0x7f800000);
        int bi = 0x7fffffff;
        for (int c = lane; c < KCODES; c += 32) {
            const float* er = cb + (size_t)c * CDIM;
            float a2 = 0.0f;
#pragma unroll 16
            for (int k = 0; k < CDIM; k++) a2 = __fmaf_rn(zS[k * 128 + row], __ldg(er + k), a2);
            float d = __fsub_rn(__fadd_rn(sz, seS[c]), __fmul_rn(2.0f, a2));
            if (d < bd) { bd = d; bi = c; }   // ascending c: strict < keeps lowest
        }
#pragma unroll
        for (int off = 16; off > 0; off >>= 1) {
            float od = __shfl_xor_sync(0xffffffffu, bd, off);
            int   oi = __shfl_xor_sync(0xffffffffu, bi, off);
            if (od < bd || (od == bd && oi < bi)) { bd = od; bi = oi; }
        }
        if (lane == 0) idxS[row] = bi;
    }
    __syncthreads();

    if (tid < 128 && !ovfS[tid] && cntmS[tid] >= 2)
        idxS[tid] = (int)(keyS[tid] & 0xffffffffu);
    __syncthreads();

    if (mode >= 2 && tid < 128)
        out[N_ZQ + 2 + m0 + tid] = (float)idxS[tid];

    // ---- fused gather: z from smem, e from L2, coalesced stores ----
    {
        const int gm = tid & 127, gh = tid >> 7;   // row, column-half
        const int idx = idxS[gm];
        const float4* er4 = (const float4*)(cb + (size_t)idx * CDIM) + gh * 32;
        float lsum = 0.0f;
#pragma unroll 4
        for (int cq = 0; cq < 32; cq++) {
            float4 e4 = er4[cq];
            int c0 = gh * 128 + cq * 4;
            float ev[4] = {e4.x, e4.y, e4.z, e4.w};
#pragma unroll
            for (int j = 0; j < 4; j++) {
                int c = c0 + j;
                float zv = zS[c * 128 + gm];
                float t  = __fsub_rn(ev[j], zv);           // e - z
                out[(((size_t)(b * CDIM + c)) << 12) + hw0 + gm] = __fadd_rn(zv, t);
                lsum = __fmaf_rn(t, t, lsum);
            }
        }
        for (int o = 16; o > 0; o >>= 1)
            lsum += __shfl_down_sync(0xffffffffu, lsum, o);
        if (lane == 0) atomicAdd(&g_loss, (double)lsum);
    }
}

__global__ void finalize_kernel(float* __restrict__ out, int mode) {
    if (mode >= 1) {
        float mean = (float)(g_loss / (double)N_ZQ);
        out[N_ZQ]     = mean;          // codebook_loss
        out[N_ZQ + 1] = 0.25f * mean;  // commitment_loss = exactly 0.25 * mean
    }
}

// ---------------------------------------------------------------------------
extern "C" void kernel_launch(void* const* d_in, const int* in_sizes, int n_in,
                              void* d_out, int out_size) {
    const float* z  = (const float*)d_in[0];
    const float* cb = (const float*)d_in[1];
    float* out = (float*)d_out;

    int mode = 0;
    if (out_size >= N_ZQ + 2) mode = 1;
    if (out_size >= N_ZQ + 2 + N_VEC) mode = 2;

    cudaFuncSetAttribute(vq_main_kernel,
                         cudaFuncAttributeMaxDynamicSharedMemorySize, SM_TOT);

    cb_prep_kernel<<<KCODES, 256>>>(cb);
    vq_main_kernel<<<N_VEC / 128, 256, SM_TOT>>>(z, cb, out, mode);
    finalize_kernel<<<1, 1>>>(out, mode);
}

// round 13
// speedup vs baseline: 82.1319x; 82.1319x over previous
#include <cuda_runtime.h>
#include <cstdint>

// Problem constants
#define NB      32
#define CDIM    256
#define HWN     4096
#define KCODES  1024
#define N_VEC   (NB * HWN)        // 131072
#define N_ZQ    (NB * CDIM * HWN) // 33554432

#define MT      64                // vectors per CTA
#define NT_N    256               // codes per n-tile
#define NTILES  (KCODES / NT_N)   // 4
#define KC      8                 // k per e-chunk
#define NCHUNK  (NTILES * CDIM / KC)  // 128 chunk iterations

// ---------------- static device scratch ----------------
// Duplicated codebook: f32 index = t*131072 + k*512 + (n&255)*2 + {0,1}
__device__ float  g_et2[KCODES * CDIM * 2];   // 2 MB
__device__ float  g_se[KCODES];               // ||e||^2
__device__ double g_loss;

#define FMA2(acc, a, b) \
    asm("fma.rn.f32x2 %0, %1, %2, %0;" : "+l"(acc) : "l"(a), "l"(b))

__device__ __forceinline__ uint32_t smem_u32(const void* p) {
    uint32_t a;
    asm("{ .reg .u64 t; cvta.to.shared.u64 t, %1; cvt.u32.u64 %0, t; }"
        : "=r"(a) : "l"(p));
    return a;
}
#define CP_ASYNC16(dst, src) \
    asm volatile("cp.async.cg.shared.global [%0], [%1], 16;" :: "r"(dst), "l"(src))
#define CP_COMMIT() asm volatile("cp.async.commit_group;" ::: "memory")
#define CP_WAIT(n)  asm volatile("cp.async.wait_group %0;" :: "n"(n) : "memory")

// ---------------------------------------------------------------------------
// Codebook prep: duplicated layout + ||e||^2 + zero loss.
// ---------------------------------------------------------------------------
__global__ void cb_prep_kernel(const float* __restrict__ cb) {
    int n = blockIdx.x, k = threadIdx.x;
    float v = cb[n * CDIM + k];
    int t = n >> 8, np = n & 255;
    int off = t * 131072 + k * 512 + np * 2;
    g_et2[off]     = v;
    g_et2[off + 1] = v;
    __shared__ float red[256];
    red[k] = __fmul_rn(v, v);
    __syncthreads();
    for (int sft = 128; sft > 0; sft >>= 1) {
        if (k < sft) red[k] = __fadd_rn(red[k], red[k + sft]);
        __syncthreads();
    }
    if (k == 0) {
        g_se[n] = red[0];
        if (n == 0) g_loss = 0.0;
    }
}

// ---------------------------------------------------------------------------
// Fused kernel: fp32x2 GEMM + exact argmin + sz + gather/loss/indices.
// 128 threads, 64 vecs x 1024 codes per CTA, 2 CTAs/SM for phase overlap.
// Per-thread 16m x 8n; dot = single serial ascending-k fp32 FMA chain.
// ---------------------------------------------------------------------------
#define SM_ZS  0         // 65536 : z fp32 [256k][64m]
#define SM_ES  65536     // 2 x 16384 : e-chunks (dup layout, [8k][512f])
#define SM_SE  98304     // 4096
#define SM_SZ  102400    // 256
#define SM_IDX 102656    // 256
#define SM_TOT 102912
#define SM_RED SM_ES     // overlay after GEMM: 64 x 33 x (4+4)B

__global__ void __launch_bounds__(128, 2)
vq_gemm_kernel(const float* __restrict__ z, const float* __restrict__ cb,
               float* __restrict__ out, int mode) {
    extern __shared__ __align__(1024) float smf[];
    char* sm = (char*)smf;
    const uint32_t sb = smem_u32(sm);
    const int tid  = threadIdx.x;
    const int w    = tid >> 5, lane = tid & 31;
    const int s    = lane >> 2;        // 0..7  (n sub-group)
    const int mc   = lane & 3;         // 0..3  (m chunk)
    const int m0 = blockIdx.x * MT;
    const int b   = m0 >> 12;
    const int hw0 = m0 & (HWN - 1);

    float* zS  = smf;
    float* seS = (float*)(sm + SM_SE);
    float* szS = (float*)(sm + SM_SZ);
    int*   idxS = (int*)(sm + SM_IDX);

    for (int i = tid; i < KCODES; i += 128) seS[i] = g_se[i];

    // z tile: [256 k][64 m] fp32, coalesced load, linear store
    for (int it = 0; it < 32; it++) {
        int idx = tid + it * 128;
        int c = idx >> 4, mq = idx & 15;
        float4 v = *(const float4*)(z + (((size_t)(b * CDIM + c)) << 12) + hw0 + (mq << 2));
        *(float4*)(zS + c * MT + (mq << 2)) = v;
    }
    // prefetch e-chunk 0 (16 KB)
#pragma unroll
    for (int it = 0; it < 8; it++) {
        int idx = tid + it * 128;
        CP_ASYNC16(sb + SM_ES + idx * 16, g_et2 + idx * 4);
    }
    CP_COMMIT();
    __syncthreads();

    // ||z||^2 in reference order: serial ascending c, unfused mul+add
    if (tid < MT) {
        float a = 0.0f;
        for (int c = 0; c < CDIM; c++) {
            float x = zS[c * MT + tid];
            a = __fadd_rn(a, __fmul_rn(x, x));
        }
        szS[tid] = a;
    }

    float bestd[16];
    int   besti[16];
#pragma unroll
    for (int i = 0; i < 16; i++) { bestd[i] = __int_as_float(0x7f800000); besti[i] = 0; }

    unsigned long long acc[64];
#pragma unroll
    for (int i = 0; i < 64; i++) acc[i] = 0ull;

    // GEMM: 128 chunks = 4 n-tiles x 32 k-chunks (KC=8)
    for (int cidx = 0; cidx < NCHUNK; cidx++) {
        if (cidx + 1 < NCHUNK) {
            const float* src = g_et2 + (size_t)((cidx + 1) >> 5) * 131072
                                     + (size_t)((cidx + 1) & 31) * (KC * 512);
            uint32_t dst = sb + SM_ES + ((cidx + 1) & 1) * 16384;
#pragma unroll
            for (int it = 0; it < 8; it++) {
                int idx = tid + it * 128;
                CP_ASYNC16(dst + idx * 16, src + idx * 4);
            }
            CP_COMMIT();
            CP_WAIT(1);   // chunk cidx complete (cidx+1 may be in flight)
        } else {
            CP_WAIT(0);
        }
        __syncthreads();  // e-chunk visible (and szS on first pass)

        const float* eT = (float*)(sm + SM_ES + (cidx & 1) * 16384);
        const int kbase = (cidx & 31) * KC;
#pragma unroll 4
        for (int kk = 0; kk < KC; kk++) {
            const float* Ak = zS + (kbase + kk) * MT + mc * 4;
            const float* Bk = eT + kk * 512 + w * 128 + s * 16;
            ulonglong2 A0 = *(const ulonglong2*)(Ak);        // m chunk i=0
            ulonglong2 A1 = *(const ulonglong2*)(Ak + 16);   // i=1
            ulonglong2 A2 = *(const ulonglong2*)(Ak + 32);   // i=2
            ulonglong2 A3 = *(const ulonglong2*)(Ak + 48);   // i=3
            ulonglong2 B0 = *(const ulonglong2*)(Bk);        // n dup-pairs
            ulonglong2 B1 = *(const ulonglong2*)(Bk + 4);
            ulonglong2 B2 = *(const ulonglong2*)(Bk + 8);
            ulonglong2 B3 = *(const ulonglong2*)(Bk + 12);
            unsigned long long av[8] = {A0.x, A0.y, A1.x, A1.y, A2.x, A2.y, A3.x, A3.y};
            unsigned long long bv[8] = {B0.x, B0.y, B1.x, B1.y, B2.x, B2.y, B3.x, B3.y};
#pragma unroll
            for (int a = 0; a < 8; a++)
#pragma unroll
                for (int c = 0; c < 8; c++)
                    FMA2(acc[a * 8 + c], av[a], bv[c]);
        }
        __syncthreads();  // compute done before buffer reuse

        if ((cidx & 31) == 31) {
            // epilogue for n-tile nt: d = fl(fl(sz+se) - 2*dot), running argmin
            const int nt = cidx >> 5;
#pragma unroll
            for (int c = 0; c < 8; c++) {
                const int n = nt * NT_N + w * 64 + s * 8 + c;
                const float se = seS[n];
#pragma unroll
                for (int a = 0; a < 8; a++) {
                    unsigned long long pk = acc[a * 8 + c];
                    float dlo = __uint_as_float((unsigned)(pk & 0xffffffffu));
                    float dhi = __uint_as_float((unsigned)(pk >> 32));
                    const int m  = (a >> 1) * 16 + mc * 4 + (a & 1) * 2;
                    const int li = a * 2;
                    float d0 = __fsub_rn(__fadd_rn(szS[m],     se), __fmul_rn(2.0f, dlo));
                    float d1 = __fsub_rn(__fadd_rn(szS[m + 1], se), __fmul_rn(2.0f, dhi));
                    if (d0 < bestd[li])     { bestd[li]     = d0; besti[li]     = n; }
                    if (d1 < bestd[li + 1]) { bestd[li + 1] = d1; besti[li + 1] = n; }
                }
            }
#pragma unroll
            for (int i = 0; i < 64; i++) acc[i] = 0ull;
        }
    }

    // cross-thread reduction: 32 participants (w,s) per m row
    __syncthreads();
    float* redD = (float*)(sm + SM_RED);            // [64][33] d
    int*   redI = (int*)(sm + SM_RED + 8448);       // [64][33] idx
    const int pid = w * 8 + s;
#pragma unroll
    for (int a = 0; a < 8; a++)
#pragma unroll
        for (int e = 0; e < 2; e++) {
            int m  = (a >> 1) * 16 + mc * 4 + (a & 1) * 2 + e;
            redD[m * 33 + pid] = bestd[a * 2 + e];
            redI[m * 33 + pid] = besti[a * 2 + e];
        }
    __syncthreads();
    if (tid < MT) {
        float bv = redD[tid * 33];
        int   bi = redI[tid * 33];
#pragma unroll
        for (int t = 1; t < 32; t++) {
            float v  = redD[tid * 33 + t];
            int   ix = redI[tid * 33 + t];
            if (v < bv || (v == bv && ix < bi)) { bv = v; bi = ix; }
        }
        idxS[tid] = bi;
        if (mode >= 2) out[N_ZQ + 2 + m0 + tid] = (float)bi;
    }
    __syncthreads();

    // ---- fused gather: z from smem, e from L2, coalesced 128B stores ----
    {
        const int gm = tid & 63, gh = tid >> 6;    // row, column-half
        const int idx = idxS[gm];
        const float4* er4 = (const float4*)(cb + (size_t)idx * CDIM) + gh * 32;
        float lsum = 0.0f;
#pragma unroll 4
        for (int cq = 0; cq < 32; cq++) {
            float4 e4 = er4[cq];
            int c0 = gh * 128 + cq * 4;
            float ev[4] = {e4.x, e4.y, e4.z, e4.w};
#pragma unroll
            for (int j = 0; j < 4; j++) {
                int c = c0 + j;
                float zv = zS[c * MT + gm];
                float t  = __fsub_rn(ev[j], zv);           // e - z
                out[(((size_t)(b * CDIM + c)) << 12) + hw0 + gm] = __fadd_rn(zv, t);
                lsum = __fmaf_rn(t, t, lsum);
            }
        }
        for (int o = 16; o > 0; o >>= 1)
            lsum += __shfl_down_sync(0xffffffffu, lsum, o);
        if (lane == 0) atomicAdd(&g_loss, (double)lsum);
    }
}

__global__ void finalize_kernel(float* __restrict__ out, int mode) {
    if (mode >= 1) {
        float mean = (float)(g_loss / (double)N_ZQ);
        out[N_ZQ]     = mean;          // codebook_loss
        out[N_ZQ + 1] = 0.25f * mean;  // commitment_loss = exactly 0.25 * mean
    }
}

// ---------------------------------------------------------------------------
extern "C" void kernel_launch(void* const* d_in, const int* in_sizes, int n_in,
                              void* d_out, int out_size) {
    const float* z  = (const float*)d_in[0];
    const float* cb = (const float*)d_in[1];
    float* out = (float*)d_out;

    int mode = 0;
    if (out_size >= N_ZQ + 2) mode = 1;
    if (out_size >= N_ZQ + 2 + N_VEC) mode = 2;

    cudaFuncSetAttribute(vq_gemm_kernel,
                         cudaFuncAttributeMaxDynamicSharedMemorySize, SM_TOT);

    cb_prep_kernel<<<KCODES, 256>>>(cb);
    vq_gemm_kernel<<<N_VEC / MT, 128, SM_TOT>>>(z, cb, out, mode);
    finalize_kernel<<<1, 1>>>(out, mode);
}